// round 4
// baseline (speedup 1.0000x reference)
#include <cuda_runtime.h>
#include <math.h>

// Problem constants
#define NTOK 50176            // 16 * 56 * 56
#define CDIM 96
#define QKVDIM 288
#define HIDDIM 384
#define LITDIM 768
#define NCLAUSE 128
#define NWIN 1024             // 16 * 8 * 8
#define IMGHW 56
#define LNEPS 1e-5f

// ---------------- scratch (static device arrays; no allocation) -------------
__device__ float g_xln[(size_t)NTOK * CDIM];
__device__ float g_qkv[(size_t)NTOK * QKVDIM];
__device__ float g_ao [(size_t)NTOK * CDIM];
__device__ float g_x1 [(size_t)NTOK * CDIM];
__device__ float g_w  [(size_t)NTOK * CDIM];
__device__ float g_ll [(size_t)NTOK * LITDIM];
__device__ float g_cl [(size_t)NTOK * NCLAUSE];

// ---------------- helpers ---------------------------------------------------
__device__ __forceinline__ float warp_sum(float v) {
#pragma unroll
    for (int o = 16; o > 0; o >>= 1) v += __shfl_xor_sync(0xffffffffu, v, o);
    return v;
}

// ---------------- LN kernels (warp per token, C = 96 = 3 * 32) ---------------
__global__ __launch_bounds__(256) void ln1_kernel(
    const float* __restrict__ x, const float* __restrict__ g,
    const float* __restrict__ b, float* __restrict__ y)
{
    int warp = (blockIdx.x * blockDim.x + threadIdx.x) >> 5;
    int lane = threadIdx.x & 31;
    if (warp >= NTOK) return;
    size_t base = (size_t)warp * CDIM;
    float v0 = x[base + lane];
    float v1 = x[base + lane + 32];
    float v2 = x[base + lane + 64];
    float mean = warp_sum(v0 + v1 + v2) * (1.0f / CDIM);
    float d0 = v0 - mean, d1 = v1 - mean, d2 = v2 - mean;
    float var = warp_sum(d0 * d0 + d1 * d1 + d2 * d2) * (1.0f / CDIM);
    float rs = rsqrtf(var + LNEPS);
    y[base + lane]      = d0 * rs * g[lane]      + b[lane];
    y[base + lane + 32] = d1 * rs * g[lane + 32] + b[lane + 32];
    y[base + lane + 64] = d2 * rs * g[lane + 64] + b[lane + 64];
}

// double layernorm: w = LN(LN(x1, g2, b2), fg, fb)
__global__ __launch_bounds__(256) void ln2_kernel(
    const float* __restrict__ x, const float* __restrict__ g2,
    const float* __restrict__ b2, const float* __restrict__ fg,
    const float* __restrict__ fb, float* __restrict__ y)
{
    int warp = (blockIdx.x * blockDim.x + threadIdx.x) >> 5;
    int lane = threadIdx.x & 31;
    if (warp >= NTOK) return;
    size_t base = (size_t)warp * CDIM;
    float v0 = x[base + lane];
    float v1 = x[base + lane + 32];
    float v2 = x[base + lane + 64];
    float mean = warp_sum(v0 + v1 + v2) * (1.0f / CDIM);
    float d0 = v0 - mean, d1 = v1 - mean, d2 = v2 - mean;
    float var = warp_sum(d0 * d0 + d1 * d1 + d2 * d2) * (1.0f / CDIM);
    float rs = rsqrtf(var + LNEPS);
    float z0 = d0 * rs * g2[lane]      + b2[lane];
    float z1 = d1 * rs * g2[lane + 32] + b2[lane + 32];
    float z2 = d2 * rs * g2[lane + 64] + b2[lane + 64];
    float m2 = warp_sum(z0 + z1 + z2) * (1.0f / CDIM);
    float e0 = z0 - m2, e1 = z1 - m2, e2 = z2 - m2;
    float var2 = warp_sum(e0 * e0 + e1 * e1 + e2 * e2) * (1.0f / CDIM);
    float rs2 = rsqrtf(var2 + LNEPS);
    y[base + lane]      = e0 * rs2 * fg[lane]      + fb[lane];
    y[base + lane + 32] = e1 * rs2 * fg[lane + 32] + fb[lane + 32];
    y[base + lane + 64] = e2 * rs2 * fg[lane + 64] + fb[lane + 64];
}

// ---------------- generic fp32 tiled GEMM with fused epilogues ---------------
// C[M x N] = A[M x K] @ op(B) (+bias) ; op(B)=B^T if !BTRANS (B is N x K),
// op(B)=B if BTRANS (B is K x N). BMASK: B element -> (B>0 ? 1 : 0).
// MODE 1: qkv       : C = acc + bias[n]
// MODE 2: proj+res  : C = ex1[m*96+n] + acc + bias[n]
// MODE 3: pin/log   : y = sigmoid(acc+bias); C[m*768+n]=log(max(y,1e-6));
//                     C[m*768+384+n]=log(max(1-y,1e-6))
// MODE 4: clauses   : C = exp(acc)
// MODE 5: final     : g = sigmoid(ex2[0]); l = acc;
//                     C = ex1[m*96+n] + g*l + (1-g)*sigmoid(l)
template<int MODE, bool BTRANS, bool BMASK>
__global__ __launch_bounds__(256) void gemm_k(
    const float* __restrict__ A, const float* __restrict__ B,
    const float* __restrict__ bias, const float* __restrict__ ex1,
    const float* __restrict__ ex2, float* __restrict__ C,
    int M, int N, int K, int ldc)
{
    const int BM = 64, BN = 64, BK = 32;
    __shared__ float As[BK][BM + 4];
    __shared__ float Bs[BK][BN + 4];

    int m0 = blockIdx.x * BM;
    int n0 = blockIdx.y * BN;
    int tid = threadIdx.x;
    int tx = tid & 15;       // 16 cols of threads -> n
    int ty = tid >> 4;       // 16 rows of threads -> m
    int kk = tid & 31;
    int rr = tid >> 5;       // 0..7

    float acc[4][4];
#pragma unroll
    for (int i = 0; i < 4; i++)
#pragma unroll
        for (int j = 0; j < 4; j++) acc[i][j] = 0.0f;

    for (int k0 = 0; k0 < K; k0 += BK) {
#pragma unroll
        for (int i = 0; i < 8; i++) {
            int mr = rr + 8 * i;                 // m within tile (M divisible by 64)
            As[kk][mr] = A[(size_t)(m0 + mr) * K + k0 + kk];
        }
#pragma unroll
        for (int i = 0; i < 8; i++) {
            int nc = rr + 8 * i;
            int n = n0 + nc;
            float v = 0.0f;
            if (n < N) {
                if (BMASK)       v = (B[(size_t)n * K + k0 + kk] > 0.0f) ? 1.0f : 0.0f;
                else if (BTRANS) v = B[(size_t)(k0 + kk) * N + n];
                else             v = B[(size_t)n * K + k0 + kk];
            }
            Bs[kk][nc] = v;
        }
        __syncthreads();
#pragma unroll
        for (int k2 = 0; k2 < BK; k2++) {
            float4 a4 = *reinterpret_cast<const float4*>(&As[k2][ty * 4]);
            float4 b4 = *reinterpret_cast<const float4*>(&Bs[k2][tx * 4]);
            float a[4] = {a4.x, a4.y, a4.z, a4.w};
            float bb[4] = {b4.x, b4.y, b4.z, b4.w};
#pragma unroll
            for (int i = 0; i < 4; i++)
#pragma unroll
                for (int j = 0; j < 4; j++) acc[i][j] += a[i] * bb[j];
        }
        __syncthreads();
    }

#pragma unroll
    for (int i = 0; i < 4; i++) {
        int m = m0 + ty * 4 + i;
#pragma unroll
        for (int j = 0; j < 4; j++) {
            int n = n0 + tx * 4 + j;
            if (n >= N) continue;
            float v = acc[i][j];
            if (MODE == 1) {
                C[(size_t)m * ldc + n] = v + bias[n];
            } else if (MODE == 2) {
                C[(size_t)m * ldc + n] = ex1[(size_t)m * CDIM + n] + v + bias[n];
            } else if (MODE == 3) {
                float y = 1.0f / (1.0f + expf(-(v + bias[n])));
                C[(size_t)m * LITDIM + n]          = logf(fmaxf(y, 1e-6f));
                C[(size_t)m * LITDIM + HIDDIM + n] = logf(fmaxf(1.0f - y, 1e-6f));
            } else if (MODE == 4) {
                C[(size_t)m * ldc + n] = expf(v);
            } else if (MODE == 5) {
                float g = 1.0f / (1.0f + expf(-ex2[0]));
                float s = 1.0f / (1.0f + expf(-v));
                C[(size_t)m * ldc + n] = ex1[(size_t)m * CDIM + n] + g * v + (1.0f - g) * s;
            }
        }
    }
}

// ---------------- windowed attention core ------------------------------------
// One block per window (1024). qkv rows: [q(96) | k(96) | v(96)], head h at
// offset h*32.
// Input gather: token (wh,ww,th,tw) reads shifted image pos
//   ((wh*7+th+3)%56, (ww*7+tw+3)%56)                      -> ltab
// Output scatter (reference rolls WITHIN each window, axes (3,4), by +3):
//   a[wh][ww][th][tw] lands at image pos
//   (wh*7 + (th+3)%7, ww*7 + (tw+3)%7)                    -> otab
__global__ __launch_bounds__(128) void attn_kernel(
    const float* __restrict__ qkv, float* __restrict__ ao)
{
    __shared__ float qs[49][33], ks[49][33], vs[49][33];
    __shared__ float ps[49][52];
    __shared__ int ltab[49];
    __shared__ int otab[49];

    int w = blockIdx.x;
    int b  = w >> 6;
    int wh = (w >> 3) & 7;
    int ww = w & 7;
    int tid = threadIdx.x;

    if (tid < 49) {
        int th = tid / 7, tw = tid % 7;
        int r = (wh * 7 + th + 3) % IMGHW;
        int c = (ww * 7 + tw + 3) % IMGHW;
        ltab[tid] = b * (IMGHW * IMGHW) + r * IMGHW + c;
        int ro = wh * 7 + (th + 3) % 7;          // intra-window inverse roll
        int co = ww * 7 + (tw + 3) % 7;
        otab[tid] = b * (IMGHW * IMGHW) + ro * IMGHW + co;
    }
    __syncthreads();

    const float scale = 0.17677669529663687f;  // 1/sqrt(32)

    for (int h = 0; h < 3; h++) {
        for (int i = tid; i < 49 * 32; i += 128) {
            int t = i >> 5, d = i & 31;
            size_t base = (size_t)ltab[t] * QKVDIM + h * 32 + d;
            qs[t][d] = qkv[base];
            ks[t][d] = qkv[base + 96];
            vs[t][d] = qkv[base + 192];
        }
        __syncthreads();

        for (int i = tid; i < 49 * 49; i += 128) {
            int r = i / 49, c = i - r * 49;
            float s = 0.0f;
#pragma unroll
            for (int d = 0; d < 32; d++) s += qs[r][d] * ks[c][d];
            ps[r][c] = s * scale;
        }
        __syncthreads();

        if (tid < 49) {
            float mx = -1e30f;
            for (int j = 0; j < 49; j++) mx = fmaxf(mx, ps[tid][j]);
            float sum = 0.0f;
            for (int j = 0; j < 49; j++) {
                float e = expf(ps[tid][j] - mx);
                ps[tid][j] = e;
                sum += e;
            }
            float inv = 1.0f / sum;
            for (int j = 0; j < 49; j++) ps[tid][j] *= inv;
        }
        __syncthreads();

        for (int i = tid; i < 49 * 32; i += 128) {
            int t = i >> 5, d = i & 31;
            float o = 0.0f;
#pragma unroll
            for (int j = 0; j < 49; j++) o += ps[t][j] * vs[j][d];
            ao[(size_t)otab[t] * CDIM + h * 32 + d] = o;
        }
        __syncthreads();
    }
}

// ---------------- host launcher ----------------------------------------------
extern "C" void kernel_launch(void* const* d_in, const int* in_sizes, int n_in,
                              void* d_out, int out_size)
{
    const float* x       = (const float*)d_in[0];
    const float* n1g     = (const float*)d_in[1];
    const float* n1b     = (const float*)d_in[2];
    const float* qkv_w   = (const float*)d_in[3];
    const float* qkv_b   = (const float*)d_in[4];
    const float* proj_w  = (const float*)d_in[5];
    const float* proj_b  = (const float*)d_in[6];
    const float* n2g     = (const float*)d_in[7];
    const float* n2b     = (const float*)d_in[8];
    const float* fng     = (const float*)d_in[9];
    const float* fnb     = (const float*)d_in[10];
    const float* pin_w   = (const float*)d_in[11];
    const float* pin_b   = (const float*)d_in[12];
    const float* tm_inc  = (const float*)d_in[13];
    const float* tm_out  = (const float*)d_in[14];
    const float* gate    = (const float*)d_in[15];
    float* out           = (float*)d_out;

    float *p_xln, *p_qkv, *p_ao, *p_x1, *p_w, *p_ll, *p_cl;
    cudaGetSymbolAddress((void**)&p_xln, g_xln);
    cudaGetSymbolAddress((void**)&p_qkv, g_qkv);
    cudaGetSymbolAddress((void**)&p_ao,  g_ao);
    cudaGetSymbolAddress((void**)&p_x1,  g_x1);
    cudaGetSymbolAddress((void**)&p_w,   g_w);
    cudaGetSymbolAddress((void**)&p_ll,  g_ll);
    cudaGetSymbolAddress((void**)&p_cl,  g_cl);

    const int MB = NTOK / 64;  // 784

    // 1) LN1
    ln1_kernel<<<NTOK / 8, 256>>>(x, n1g, n1b, p_xln);

    // 2) QKV GEMM: (50176 x 96) @ (288 x 96)^T + b  -> g_qkv
    gemm_k<1, false, false><<<dim3(MB, (QKVDIM + 63) / 64), 256>>>(
        p_xln, qkv_w, qkv_b, nullptr, nullptr, p_qkv,
        NTOK, QKVDIM, CDIM, QKVDIM);

    // 3) windowed attention core -> g_ao
    attn_kernel<<<NWIN, 128>>>(p_qkv, p_ao);

    // 4) proj + residual: x1 = x + ao @ proj_w^T + b
    gemm_k<2, false, false><<<dim3(MB, (CDIM + 63) / 64), 256>>>(
        p_ao, proj_w, proj_b, x, nullptr, p_x1,
        NTOK, CDIM, CDIM, CDIM);

    // 5) double layernorm -> g_w
    ln2_kernel<<<NTOK / 8, 256>>>(p_x1, n2g, n2b, fng, fnb, p_w);

    // 6) pin GEMM + sigmoid + log-literals -> g_ll (token x 768)
    gemm_k<3, false, false><<<dim3(MB, (HIDDIM + 63) / 64), 256>>>(
        p_w, pin_w, pin_b, nullptr, nullptr, p_ll,
        NTOK, HIDDIM, CDIM, LITDIM);

    // 7) clause GEMM with binary mask (tm_inc > 0), exp epilogue -> g_cl
    gemm_k<4, false, true><<<dim3(MB, (NCLAUSE + 63) / 64), 256>>>(
        p_ll, tm_inc, nullptr, nullptr, nullptr, p_cl,
        NTOK, NCLAUSE, LITDIM, NCLAUSE);

    // 8) logits = clauses @ tm_out (K x N layout), gated output + residual
    gemm_k<5, true, false><<<dim3(MB, (CDIM + 63) / 64), 256>>>(
        p_cl, tm_out, nullptr, p_x1, gate, out,
        NTOK, CDIM, NCLAUSE, CDIM);

    (void)in_sizes; (void)n_in; (void)out_size;
}

// round 5
// speedup vs baseline: 1.1203x; 1.1203x over previous
#include <cuda_runtime.h>
#include <math.h>

// Problem constants
#define NTOK 50176            // 16 * 56 * 56
#define CDIM 96
#define QKVDIM 288
#define HIDDIM 384
#define LITDIM 768
#define NCLAUSE 128
#define NWIN 1024             // 16 * 8 * 8
#define IMGHW 56
#define LNEPS 1e-5f

// ---------------- scratch (static device arrays; no allocation) -------------
__device__ float g_xln[(size_t)NTOK * CDIM];
__device__ float g_qkv[(size_t)NTOK * QKVDIM];
__device__ float g_ao [(size_t)NTOK * CDIM];
__device__ float g_x1 [(size_t)NTOK * CDIM];
__device__ float g_w  [(size_t)NTOK * CDIM];
__device__ float g_ll [(size_t)NTOK * LITDIM];
__device__ float g_cl [(size_t)NTOK * NCLAUSE];

// ---------------- helpers ---------------------------------------------------
__device__ __forceinline__ float warp_sum(float v) {
#pragma unroll
    for (int o = 16; o > 0; o >>= 1) v += __shfl_xor_sync(0xffffffffu, v, o);
    return v;
}

// ---------------- LN kernels (warp per token, C = 96 = 3 * 32) ---------------
__global__ __launch_bounds__(256) void ln1_kernel(
    const float* __restrict__ x, const float* __restrict__ g,
    const float* __restrict__ b, float* __restrict__ y)
{
    int warp = (blockIdx.x * blockDim.x + threadIdx.x) >> 5;
    int lane = threadIdx.x & 31;
    if (warp >= NTOK) return;
    size_t base = (size_t)warp * CDIM;
    float v0 = x[base + lane];
    float v1 = x[base + lane + 32];
    float v2 = x[base + lane + 64];
    float mean = warp_sum(v0 + v1 + v2) * (1.0f / CDIM);
    float d0 = v0 - mean, d1 = v1 - mean, d2 = v2 - mean;
    float var = warp_sum(d0 * d0 + d1 * d1 + d2 * d2) * (1.0f / CDIM);
    float rs = rsqrtf(var + LNEPS);
    y[base + lane]      = d0 * rs * g[lane]      + b[lane];
    y[base + lane + 32] = d1 * rs * g[lane + 32] + b[lane + 32];
    y[base + lane + 64] = d2 * rs * g[lane + 64] + b[lane + 64];
}

// double layernorm: w = LN(LN(x1, g2, b2), fg, fb)
__global__ __launch_bounds__(256) void ln2_kernel(
    const float* __restrict__ x, const float* __restrict__ g2,
    const float* __restrict__ b2, const float* __restrict__ fg,
    const float* __restrict__ fb, float* __restrict__ y)
{
    int warp = (blockIdx.x * blockDim.x + threadIdx.x) >> 5;
    int lane = threadIdx.x & 31;
    if (warp >= NTOK) return;
    size_t base = (size_t)warp * CDIM;
    float v0 = x[base + lane];
    float v1 = x[base + lane + 32];
    float v2 = x[base + lane + 64];
    float mean = warp_sum(v0 + v1 + v2) * (1.0f / CDIM);
    float d0 = v0 - mean, d1 = v1 - mean, d2 = v2 - mean;
    float var = warp_sum(d0 * d0 + d1 * d1 + d2 * d2) * (1.0f / CDIM);
    float rs = rsqrtf(var + LNEPS);
    float z0 = d0 * rs * g2[lane]      + b2[lane];
    float z1 = d1 * rs * g2[lane + 32] + b2[lane + 32];
    float z2 = d2 * rs * g2[lane + 64] + b2[lane + 64];
    float m2 = warp_sum(z0 + z1 + z2) * (1.0f / CDIM);
    float e0 = z0 - m2, e1 = z1 - m2, e2 = z2 - m2;
    float var2 = warp_sum(e0 * e0 + e1 * e1 + e2 * e2) * (1.0f / CDIM);
    float rs2 = rsqrtf(var2 + LNEPS);
    y[base + lane]      = e0 * rs2 * fg[lane]      + fb[lane];
    y[base + lane + 32] = e1 * rs2 * fg[lane + 32] + fb[lane + 32];
    y[base + lane + 64] = e2 * rs2 * fg[lane + 64] + fb[lane + 64];
}

// ---------------- fp32 tiled GEMM, 128x128x16, 8x8 micro, double-buffered ----
// C[M x N] = A[M x K] @ op(B) (+bias) ; op(B)=B^T if !BTRANS (B is N x K),
// op(B)=B if BTRANS (B is K x N). BMASK: B element -> (B>0 ? 1 : 0).
// MODE 1: qkv       : C = acc + bias[n]
// MODE 2: proj+res  : C = ex1[m*96+n] + acc + bias[n]
// MODE 3: pin/log   : y = sigmoid(acc+bias); C[m*768+n]=log(max(y,1e-6));
//                     C[m*768+384+n]=log(max(1-y,1e-6))
// MODE 4: clauses   : C = exp(acc)
// MODE 5: final     : g = sigmoid(ex2[0]); l = acc;
//                     C = ex1[m*96+n] + g*l + (1-g)*sigmoid(l)
// Requires: M % 128 == 0, K % 16 == 0. N arbitrary (guarded).
template<int MODE, bool BTRANS, bool BMASK>
__global__ __launch_bounds__(256) void gemm2_k(
    const float* __restrict__ A, const float* __restrict__ B,
    const float* __restrict__ bias, const float* __restrict__ ex1,
    const float* __restrict__ ex2, float* __restrict__ C,
    int M, int N, int K, int ldc)
{
    const int BM = 128, BN = 128, BK = 16;
    __shared__ __align__(16) float As[2][BK][BM + 4];
    __shared__ __align__(16) float Bs[2][BK][BN + 4];

    int tid = threadIdx.x;
    int m0 = blockIdx.x * BM;
    int n0 = blockIdx.y * BN;
    int tx = tid & 15;        // n group
    int ty = tid >> 4;        // m group

    int lr = tid >> 1;        // row within tile for A/B(NxK) loads (0..127)
    int lk = (tid & 1) * 8;   // k offset (0 or 8)
    int bk = tid >> 4;        // k row for BTRANS B loads (0..15)
    int bn = (tid & 15) * 8;  // n offset for BTRANS B loads

    float acc[8][8];
#pragma unroll
    for (int i = 0; i < 8; i++)
#pragma unroll
        for (int j = 0; j < 8; j++) acc[i][j] = 0.0f;

    float ldA[8], ldB[8];
    int KT = K / BK;

#define GEMM_LOAD(kt)                                                        \
    {                                                                        \
        const float* ap = A + (size_t)(m0 + lr) * K + (kt) * BK + lk;        \
        float4 u = *(const float4*)ap;                                       \
        float4 v = *(const float4*)(ap + 4);                                 \
        ldA[0]=u.x; ldA[1]=u.y; ldA[2]=u.z; ldA[3]=u.w;                      \
        ldA[4]=v.x; ldA[5]=v.y; ldA[6]=v.z; ldA[7]=v.w;                      \
        if (!BTRANS) {                                                       \
            int n = n0 + lr;                                                 \
            if (n < N) {                                                     \
                const float* bp = B + (size_t)n * K + (kt) * BK + lk;        \
                float4 s = *(const float4*)bp;                               \
                float4 t = *(const float4*)(bp + 4);                         \
                ldB[0]=s.x; ldB[1]=s.y; ldB[2]=s.z; ldB[3]=s.w;              \
                ldB[4]=t.x; ldB[5]=t.y; ldB[6]=t.z; ldB[7]=t.w;              \
            } else {                                                         \
                _Pragma("unroll")                                            \
                for (int j = 0; j < 8; j++) ldB[j] = 0.0f;                   \
            }                                                                \
            if (BMASK) {                                                     \
                _Pragma("unroll")                                            \
                for (int j = 0; j < 8; j++)                                  \
                    ldB[j] = (ldB[j] > 0.0f) ? 1.0f : 0.0f;                  \
            }                                                                \
        } else {                                                             \
            _Pragma("unroll")                                                \
            for (int j = 0; j < 8; j++) {                                    \
                int n = n0 + bn + j;                                         \
                ldB[j] = (n < N)                                             \
                    ? B[(size_t)((kt) * BK + bk) * N + n] : 0.0f;            \
            }                                                                \
        }                                                                    \
    }

#define GEMM_STS(bsel)                                                       \
    {                                                                        \
        _Pragma("unroll")                                                    \
        for (int j = 0; j < 8; j++) As[bsel][lk + j][lr] = ldA[j];           \
        if (!BTRANS) {                                                       \
            _Pragma("unroll")                                                \
            for (int j = 0; j < 8; j++) Bs[bsel][lk + j][lr] = ldB[j];       \
        } else {                                                             \
            _Pragma("unroll")                                                \
            for (int j = 0; j < 8; j++) Bs[bsel][bk][bn + j] = ldB[j];       \
        }                                                                    \
    }

    GEMM_LOAD(0);
    GEMM_STS(0);
    __syncthreads();

    int buf = 0;
    for (int kt = 0; kt < KT; kt++) {
        if (kt + 1 < KT) GEMM_LOAD(kt + 1);
#pragma unroll
        for (int k = 0; k < BK; k++) {
            float4 a0 = *(const float4*)&As[buf][k][ty * 4];
            float4 a1 = *(const float4*)&As[buf][k][ty * 4 + 64];
            float4 b0 = *(const float4*)&Bs[buf][k][tx * 4];
            float4 b1 = *(const float4*)&Bs[buf][k][tx * 4 + 64];
            float a[8] = {a0.x, a0.y, a0.z, a0.w, a1.x, a1.y, a1.z, a1.w};
            float b[8] = {b0.x, b0.y, b0.z, b0.w, b1.x, b1.y, b1.z, b1.w};
#pragma unroll
            for (int i = 0; i < 8; i++)
#pragma unroll
                for (int j = 0; j < 8; j++) acc[i][j] += a[i] * b[j];
        }
        if (kt + 1 < KT) {
            GEMM_STS(buf ^ 1);
            __syncthreads();
        }
        buf ^= 1;
    }

    // epilogue
#pragma unroll
    for (int i = 0; i < 8; i++) {
        int m = m0 + ty * 4 + (i < 4 ? i : 60 + i);  // i>=4 -> +64+(i-4)
#pragma unroll
        for (int j = 0; j < 8; j++) {
            int n = n0 + tx * 4 + (j < 4 ? j : 60 + j);
            if (n >= N) continue;
            float v = acc[i][j];
            if (MODE == 1) {
                C[(size_t)m * ldc + n] = v + bias[n];
            } else if (MODE == 2) {
                C[(size_t)m * ldc + n] = ex1[(size_t)m * CDIM + n] + v + bias[n];
            } else if (MODE == 3) {
                float y = 1.0f / (1.0f + expf(-(v + bias[n])));
                C[(size_t)m * LITDIM + n]          = logf(fmaxf(y, 1e-6f));
                C[(size_t)m * LITDIM + HIDDIM + n] = logf(fmaxf(1.0f - y, 1e-6f));
            } else if (MODE == 4) {
                C[(size_t)m * ldc + n] = expf(v);
            } else if (MODE == 5) {
                float g = 1.0f / (1.0f + expf(-ex2[0]));
                float s = 1.0f / (1.0f + expf(-v));
                C[(size_t)m * ldc + n] = ex1[(size_t)m * CDIM + n] + g * v + (1.0f - g) * s;
            }
        }
    }
#undef GEMM_LOAD
#undef GEMM_STS
}

// ---------------- windowed attention core ------------------------------------
// One block per window (1024). qkv rows: [q(96) | k(96) | v(96)], head h at
// offset h*32.
// Input gather: token (wh,ww,th,tw) reads shifted image pos
//   ((wh*7+th+3)%56, (ww*7+tw+3)%56)                      -> ltab
// Output scatter (reference rolls WITHIN each window, axes (3,4), by +3):
//   a[wh][ww][th][tw] lands at image pos
//   (wh*7 + (th+3)%7, ww*7 + (tw+3)%7)                    -> otab
__global__ __launch_bounds__(128) void attn_kernel(
    const float* __restrict__ qkv, float* __restrict__ ao)
{
    __shared__ float qs[49][33], ks[49][33], vs[49][33];
    __shared__ float ps[49][52];
    __shared__ int ltab[49];
    __shared__ int otab[49];

    int w = blockIdx.x;
    int b  = w >> 6;
    int wh = (w >> 3) & 7;
    int ww = w & 7;
    int tid = threadIdx.x;

    if (tid < 49) {
        int th = tid / 7, tw = tid % 7;
        int r = (wh * 7 + th + 3) % IMGHW;
        int c = (ww * 7 + tw + 3) % IMGHW;
        ltab[tid] = b * (IMGHW * IMGHW) + r * IMGHW + c;
        int ro = wh * 7 + (th + 3) % 7;          // intra-window inverse roll
        int co = ww * 7 + (tw + 3) % 7;
        otab[tid] = b * (IMGHW * IMGHW) + ro * IMGHW + co;
    }
    __syncthreads();

    const float scale = 0.17677669529663687f;  // 1/sqrt(32)

    for (int h = 0; h < 3; h++) {
        for (int i = tid; i < 49 * 32; i += 128) {
            int t = i >> 5, d = i & 31;
            size_t base = (size_t)ltab[t] * QKVDIM + h * 32 + d;
            qs[t][d] = qkv[base];
            ks[t][d] = qkv[base + 96];
            vs[t][d] = qkv[base + 192];
        }
        __syncthreads();

        for (int i = tid; i < 49 * 49; i += 128) {
            int r = i / 49, c = i - r * 49;
            float s = 0.0f;
#pragma unroll
            for (int d = 0; d < 32; d++) s += qs[r][d] * ks[c][d];
            ps[r][c] = s * scale;
        }
        __syncthreads();

        if (tid < 49) {
            float mx = -1e30f;
            for (int j = 0; j < 49; j++) mx = fmaxf(mx, ps[tid][j]);
            float sum = 0.0f;
            for (int j = 0; j < 49; j++) {
                float e = expf(ps[tid][j] - mx);
                ps[tid][j] = e;
                sum += e;
            }
            float inv = 1.0f / sum;
            for (int j = 0; j < 49; j++) ps[tid][j] *= inv;
        }
        __syncthreads();

        for (int i = tid; i < 49 * 32; i += 128) {
            int t = i >> 5, d = i & 31;
            float o = 0.0f;
#pragma unroll
            for (int j = 0; j < 49; j++) o += ps[t][j] * vs[j][d];
            ao[(size_t)otab[t] * CDIM + h * 32 + d] = o;
        }
        __syncthreads();
    }
}

// ---------------- host launcher ----------------------------------------------
extern "C" void kernel_launch(void* const* d_in, const int* in_sizes, int n_in,
                              void* d_out, int out_size)
{
    const float* x       = (const float*)d_in[0];
    const float* n1g     = (const float*)d_in[1];
    const float* n1b     = (const float*)d_in[2];
    const float* qkv_w   = (const float*)d_in[3];
    const float* qkv_b   = (const float*)d_in[4];
    const float* proj_w  = (const float*)d_in[5];
    const float* proj_b  = (const float*)d_in[6];
    const float* n2g     = (const float*)d_in[7];
    const float* n2b     = (const float*)d_in[8];
    const float* fng     = (const float*)d_in[9];
    const float* fnb     = (const float*)d_in[10];
    const float* pin_w   = (const float*)d_in[11];
    const float* pin_b   = (const float*)d_in[12];
    const float* tm_inc  = (const float*)d_in[13];
    const float* tm_out  = (const float*)d_in[14];
    const float* gate    = (const float*)d_in[15];
    float* out           = (float*)d_out;

    float *p_xln, *p_qkv, *p_ao, *p_x1, *p_w, *p_ll, *p_cl;
    cudaGetSymbolAddress((void**)&p_xln, g_xln);
    cudaGetSymbolAddress((void**)&p_qkv, g_qkv);
    cudaGetSymbolAddress((void**)&p_ao,  g_ao);
    cudaGetSymbolAddress((void**)&p_x1,  g_x1);
    cudaGetSymbolAddress((void**)&p_w,   g_w);
    cudaGetSymbolAddress((void**)&p_ll,  g_ll);
    cudaGetSymbolAddress((void**)&p_cl,  g_cl);

    const int MB = NTOK / 128;  // 392

    // 1) LN1
    ln1_kernel<<<NTOK / 8, 256>>>(x, n1g, n1b, p_xln);

    // 2) QKV GEMM: (50176 x 96) @ (288 x 96)^T + b  -> g_qkv
    gemm2_k<1, false, false><<<dim3(MB, (QKVDIM + 127) / 128), 256>>>(
        p_xln, qkv_w, qkv_b, nullptr, nullptr, p_qkv,
        NTOK, QKVDIM, CDIM, QKVDIM);

    // 3) windowed attention core -> g_ao
    attn_kernel<<<NWIN, 128>>>(p_qkv, p_ao);

    // 4) proj + residual: x1 = x + ao @ proj_w^T + b
    gemm2_k<2, false, false><<<dim3(MB, 1), 256>>>(
        p_ao, proj_w, proj_b, x, nullptr, p_x1,
        NTOK, CDIM, CDIM, CDIM);

    // 5) double layernorm -> g_w
    ln2_kernel<<<NTOK / 8, 256>>>(p_x1, n2g, n2b, fng, fnb, p_w);

    // 6) pin GEMM + sigmoid + log-literals -> g_ll (token x 768)
    gemm2_k<3, false, false><<<dim3(MB, (HIDDIM + 127) / 128), 256>>>(
        p_w, pin_w, pin_b, nullptr, nullptr, p_ll,
        NTOK, HIDDIM, CDIM, LITDIM);

    // 7) clause GEMM with binary mask (tm_inc > 0), exp epilogue -> g_cl
    gemm2_k<4, false, true><<<dim3(MB, 1), 256>>>(
        p_ll, tm_inc, nullptr, nullptr, nullptr, p_cl,
        NTOK, NCLAUSE, LITDIM, NCLAUSE);

    // 8) logits = clauses @ tm_out (K x N layout), gated output + residual
    gemm2_k<5, true, false><<<dim3(MB, 1), 256>>>(
        p_cl, tm_out, nullptr, p_x1, gate, out,
        NTOK, CDIM, NCLAUSE, CDIM);

    (void)in_sizes; (void)n_in; (void)out_size;
}

// round 6
// speedup vs baseline: 1.1628x; 1.0380x over previous
#include <cuda_runtime.h>
#include <math.h>

// Problem constants
#define NTOK 50176            // 16 * 56 * 56
#define CDIM 96
#define QKVDIM 288
#define HIDDIM 384
#define LITDIM 768
#define NCLAUSE 128
#define NWIN 1024             // 16 * 8 * 8
#define IMGHW 56
#define LNEPS 1e-5f

// ---------------- scratch (static device arrays; no allocation) -------------
__device__ float g_xln[(size_t)NTOK * CDIM];
__device__ float g_qkv[(size_t)NTOK * QKVDIM];
__device__ float g_ao [(size_t)NTOK * CDIM];
__device__ float g_x1 [(size_t)NTOK * CDIM];
__device__ float g_w  [(size_t)NTOK * CDIM];
__device__ float g_ll [(size_t)NTOK * LITDIM];
__device__ float g_cl [(size_t)NTOK * NCLAUSE];

// ---------------- helpers ---------------------------------------------------
__device__ __forceinline__ float warp_sum(float v) {
#pragma unroll
    for (int o = 16; o > 0; o >>= 1) v += __shfl_xor_sync(0xffffffffu, v, o);
    return v;
}

// ---------------- LN kernels (warp per token, C = 96 = 3 * 32) ---------------
__global__ __launch_bounds__(256) void ln1_kernel(
    const float* __restrict__ x, const float* __restrict__ g,
    const float* __restrict__ b, float* __restrict__ y)
{
    int warp = (blockIdx.x * blockDim.x + threadIdx.x) >> 5;
    int lane = threadIdx.x & 31;
    if (warp >= NTOK) return;
    size_t base = (size_t)warp * CDIM;
    float v0 = x[base + lane];
    float v1 = x[base + lane + 32];
    float v2 = x[base + lane + 64];
    float mean = warp_sum(v0 + v1 + v2) * (1.0f / CDIM);
    float d0 = v0 - mean, d1 = v1 - mean, d2 = v2 - mean;
    float var = warp_sum(d0 * d0 + d1 * d1 + d2 * d2) * (1.0f / CDIM);
    float rs = rsqrtf(var + LNEPS);
    y[base + lane]      = d0 * rs * g[lane]      + b[lane];
    y[base + lane + 32] = d1 * rs * g[lane + 32] + b[lane + 32];
    y[base + lane + 64] = d2 * rs * g[lane + 64] + b[lane + 64];
}

// double layernorm: w = LN(LN(x1, g2, b2), fg, fb)
__global__ __launch_bounds__(256) void ln2_kernel(
    const float* __restrict__ x, const float* __restrict__ g2,
    const float* __restrict__ b2, const float* __restrict__ fg,
    const float* __restrict__ fb, float* __restrict__ y)
{
    int warp = (blockIdx.x * blockDim.x + threadIdx.x) >> 5;
    int lane = threadIdx.x & 31;
    if (warp >= NTOK) return;
    size_t base = (size_t)warp * CDIM;
    float v0 = x[base + lane];
    float v1 = x[base + lane + 32];
    float v2 = x[base + lane + 64];
    float mean = warp_sum(v0 + v1 + v2) * (1.0f / CDIM);
    float d0 = v0 - mean, d1 = v1 - mean, d2 = v2 - mean;
    float var = warp_sum(d0 * d0 + d1 * d1 + d2 * d2) * (1.0f / CDIM);
    float rs = rsqrtf(var + LNEPS);
    float z0 = d0 * rs * g2[lane]      + b2[lane];
    float z1 = d1 * rs * g2[lane + 32] + b2[lane + 32];
    float z2 = d2 * rs * g2[lane + 64] + b2[lane + 64];
    float m2 = warp_sum(z0 + z1 + z2) * (1.0f / CDIM);
    float e0 = z0 - m2, e1 = z1 - m2, e2 = z2 - m2;
    float var2 = warp_sum(e0 * e0 + e1 * e1 + e2 * e2) * (1.0f / CDIM);
    float rs2 = rsqrtf(var2 + LNEPS);
    y[base + lane]      = e0 * rs2 * fg[lane]      + fb[lane];
    y[base + lane + 32] = e1 * rs2 * fg[lane + 32] + fb[lane + 32];
    y[base + lane + 64] = e2 * rs2 * fg[lane + 64] + fb[lane + 64];
}

// ---------------- fp32 tiled GEMM, 128x128x16, 8x8 micro, double-buffered ----
// 2 CTAs/SM (128-reg cap) so barriers/loads overlap across CTAs.
// C[M x N] = A[M x K] @ op(B) (+bias) ; op(B)=B^T if !BTRANS (B is N x K),
// op(B)=B if BTRANS (B is K x N). BMASK: B element -> (B>0 ? 1 : 0).
// MODE 1: qkv       : C = acc + bias[n]
// MODE 2: proj+res  : C = ex1[m*96+n] + acc + bias[n]
// MODE 3: pin/log   : y = sigmoid(acc+bias); C[m*768+n]=log(max(y,1e-6));
//                     C[m*768+384+n]=log(max(1-y,1e-6))
// MODE 4: clauses   : C = exp(acc)
// MODE 5: final     : g = sigmoid(ex2[0]); l = acc;
//                     C = ex1[m*96+n] + g*l + (1-g)*sigmoid(l)
// Requires: M % 128 == 0, K % 16 == 0. N arbitrary (guarded).
template<int MODE, bool BTRANS, bool BMASK>
__global__ __launch_bounds__(256, 2) void gemm2_k(
    const float* __restrict__ A, const float* __restrict__ B,
    const float* __restrict__ bias, const float* __restrict__ ex1,
    const float* __restrict__ ex2, float* __restrict__ C,
    int M, int N, int K, int ldc)
{
    const int BM = 128, BN = 128, BK = 16;
    __shared__ __align__(16) float As[2][BK][BM + 4];
    __shared__ __align__(16) float Bs[2][BK][BN + 4];

    int tid = threadIdx.x;
    int m0 = blockIdx.x * BM;
    int n0 = blockIdx.y * BN;
    int tx = tid & 15;        // n group
    int ty = tid >> 4;        // m group

    int lr = tid >> 1;        // row within tile for A/B(NxK) loads (0..127)
    int lk = (tid & 1) * 8;   // k offset (0 or 8)
    int bk = tid >> 4;        // k row for BTRANS B loads (0..15)
    int bn = (tid & 15) * 8;  // n offset for BTRANS B loads

    float acc[8][8];
#pragma unroll
    for (int i = 0; i < 8; i++)
#pragma unroll
        for (int j = 0; j < 8; j++) acc[i][j] = 0.0f;

    float ldA[8], ldB[8];
    int KT = K / BK;

#define GEMM_LOAD(kt)                                                        \
    {                                                                        \
        const float* ap = A + (size_t)(m0 + lr) * K + (kt) * BK + lk;        \
        *(float4*)&ldA[0] = *(const float4*)ap;                              \
        *(float4*)&ldA[4] = *(const float4*)(ap + 4);                        \
        if (!BTRANS) {                                                       \
            int n = n0 + lr;                                                 \
            if (n < N) {                                                     \
                const float* bp = B + (size_t)n * K + (kt) * BK + lk;        \
                *(float4*)&ldB[0] = *(const float4*)bp;                      \
                *(float4*)&ldB[4] = *(const float4*)(bp + 4);                \
            } else {                                                         \
                _Pragma("unroll")                                            \
                for (int j = 0; j < 8; j++) ldB[j] = 0.0f;                   \
            }                                                                \
            if (BMASK) {                                                     \
                _Pragma("unroll")                                            \
                for (int j = 0; j < 8; j++)                                  \
                    ldB[j] = (ldB[j] > 0.0f) ? 1.0f : 0.0f;                  \
            }                                                                \
        } else {                                                             \
            _Pragma("unroll")                                                \
            for (int j = 0; j < 8; j++) {                                    \
                int n = n0 + bn + j;                                         \
                ldB[j] = (n < N)                                             \
                    ? B[(size_t)((kt) * BK + bk) * N + n] : 0.0f;            \
            }                                                                \
        }                                                                    \
    }

#define GEMM_STS(bsel)                                                       \
    {                                                                        \
        _Pragma("unroll")                                                    \
        for (int j = 0; j < 8; j++) As[bsel][lk + j][lr] = ldA[j];           \
        if (!BTRANS) {                                                       \
            _Pragma("unroll")                                                \
            for (int j = 0; j < 8; j++) Bs[bsel][lk + j][lr] = ldB[j];       \
        } else {                                                             \
            _Pragma("unroll")                                                \
            for (int j = 0; j < 8; j++) Bs[bsel][bk][bn + j] = ldB[j];       \
        }                                                                    \
    }

    GEMM_LOAD(0);
    GEMM_STS(0);
    __syncthreads();

    int buf = 0;
    for (int kt = 0; kt < KT; kt++) {
        if (kt + 1 < KT) GEMM_LOAD(kt + 1);
#pragma unroll
        for (int k = 0; k < BK; k++) {
            float4 a0 = *(const float4*)&As[buf][k][ty * 4];
            float4 a1 = *(const float4*)&As[buf][k][ty * 4 + 64];
            float4 b0 = *(const float4*)&Bs[buf][k][tx * 4];
            float4 b1 = *(const float4*)&Bs[buf][k][tx * 4 + 64];
            float a[8] = {a0.x, a0.y, a0.z, a0.w, a1.x, a1.y, a1.z, a1.w};
            float b[8] = {b0.x, b0.y, b0.z, b0.w, b1.x, b1.y, b1.z, b1.w};
#pragma unroll
            for (int i = 0; i < 8; i++)
#pragma unroll
                for (int j = 0; j < 8; j++) acc[i][j] += a[i] * b[j];
        }
        if (kt + 1 < KT) {
            GEMM_STS(buf ^ 1);
            __syncthreads();
        }
        buf ^= 1;
    }

    // epilogue
    float gte = 0.0f;
    if (MODE == 5) gte = 1.0f / (1.0f + expf(-ex2[0]));
#pragma unroll
    for (int i = 0; i < 8; i++) {
        int m = m0 + ty * 4 + (i < 4 ? i : 60 + i);  // i>=4 -> +64+(i-4)
#pragma unroll
        for (int j = 0; j < 8; j++) {
            int n = n0 + tx * 4 + (j < 4 ? j : 60 + j);
            if (n >= N) continue;
            float v = acc[i][j];
            if (MODE == 1) {
                C[(size_t)m * ldc + n] = v + bias[n];
            } else if (MODE == 2) {
                C[(size_t)m * ldc + n] = ex1[(size_t)m * CDIM + n] + v + bias[n];
            } else if (MODE == 3) {
                float y = 1.0f / (1.0f + expf(-(v + bias[n])));
                C[(size_t)m * LITDIM + n]          = logf(fmaxf(y, 1e-6f));
                C[(size_t)m * LITDIM + HIDDIM + n] = logf(fmaxf(1.0f - y, 1e-6f));
            } else if (MODE == 4) {
                C[(size_t)m * ldc + n] = expf(v);
            } else if (MODE == 5) {
                float s = 1.0f / (1.0f + expf(-v));
                C[(size_t)m * ldc + n] = ex1[(size_t)m * CDIM + n] + gte * v + (1.0f - gte) * s;
            }
        }
    }
#undef GEMM_LOAD
#undef GEMM_STS
}

// ---------------- windowed attention core ------------------------------------
// One block per window (1024). qkv rows: [q(96) | k(96) | v(96)], head h at
// offset h*32.
// Input gather: token (wh,ww,th,tw) reads shifted image pos
//   ((wh*7+th+3)%56, (ww*7+tw+3)%56)                      -> ltab
// Output scatter (reference rolls WITHIN each window, axes (3,4), by +3):
//   a[wh][ww][th][tw] lands at image pos
//   (wh*7 + (th+3)%7, ww*7 + (tw+3)%7)                    -> otab
__global__ __launch_bounds__(128) void attn_kernel(
    const float* __restrict__ qkv, float* __restrict__ ao)
{
    __shared__ float qs[49][33], ks[49][33], vs[49][33];
    __shared__ float ps[49][52];
    __shared__ int ltab[49];
    __shared__ int otab[49];

    int w = blockIdx.x;
    int b  = w >> 6;
    int wh = (w >> 3) & 7;
    int ww = w & 7;
    int tid = threadIdx.x;

    if (tid < 49) {
        int th = tid / 7, tw = tid % 7;
        int r = (wh * 7 + th + 3) % IMGHW;
        int c = (ww * 7 + tw + 3) % IMGHW;
        ltab[tid] = b * (IMGHW * IMGHW) + r * IMGHW + c;
        int ro = wh * 7 + (th + 3) % 7;          // intra-window inverse roll
        int co = ww * 7 + (tw + 3) % 7;
        otab[tid] = b * (IMGHW * IMGHW) + ro * IMGHW + co;
    }
    __syncthreads();

    const float scale = 0.17677669529663687f;  // 1/sqrt(32)

    for (int h = 0; h < 3; h++) {
        for (int i = tid; i < 49 * 32; i += 128) {
            int t = i >> 5, d = i & 31;
            size_t base = (size_t)ltab[t] * QKVDIM + h * 32 + d;
            qs[t][d] = qkv[base];
            ks[t][d] = qkv[base + 96];
            vs[t][d] = qkv[base + 192];
        }
        __syncthreads();

        for (int i = tid; i < 49 * 49; i += 128) {
            int r = i / 49, c = i - r * 49;
            float s = 0.0f;
#pragma unroll
            for (int d = 0; d < 32; d++) s += qs[r][d] * ks[c][d];
            ps[r][c] = s * scale;
        }
        __syncthreads();

        if (tid < 49) {
            float mx = -1e30f;
            for (int j = 0; j < 49; j++) mx = fmaxf(mx, ps[tid][j]);
            float sum = 0.0f;
            for (int j = 0; j < 49; j++) {
                float e = expf(ps[tid][j] - mx);
                ps[tid][j] = e;
                sum += e;
            }
            float inv = 1.0f / sum;
            for (int j = 0; j < 49; j++) ps[tid][j] *= inv;
        }
        __syncthreads();

        for (int i = tid; i < 49 * 32; i += 128) {
            int t = i >> 5, d = i & 31;
            float o = 0.0f;
#pragma unroll
            for (int j = 0; j < 49; j++) o += ps[t][j] * vs[j][d];
            ao[(size_t)otab[t] * CDIM + h * 32 + d] = o;
        }
        __syncthreads();
    }
}

// ---------------- host launcher ----------------------------------------------
extern "C" void kernel_launch(void* const* d_in, const int* in_sizes, int n_in,
                              void* d_out, int out_size)
{
    const float* x       = (const float*)d_in[0];
    const float* n1g     = (const float*)d_in[1];
    const float* n1b     = (const float*)d_in[2];
    const float* qkv_w   = (const float*)d_in[3];
    const float* qkv_b   = (const float*)d_in[4];
    const float* proj_w  = (const float*)d_in[5];
    const float* proj_b  = (const float*)d_in[6];
    const float* n2g     = (const float*)d_in[7];
    const float* n2b     = (const float*)d_in[8];
    const float* fng     = (const float*)d_in[9];
    const float* fnb     = (const float*)d_in[10];
    const float* pin_w   = (const float*)d_in[11];
    const float* pin_b   = (const float*)d_in[12];
    const float* tm_inc  = (const float*)d_in[13];
    const float* tm_out  = (const float*)d_in[14];
    const float* gate    = (const float*)d_in[15];
    float* out           = (float*)d_out;

    float *p_xln, *p_qkv, *p_ao, *p_x1, *p_w, *p_ll, *p_cl;
    cudaGetSymbolAddress((void**)&p_xln, g_xln);
    cudaGetSymbolAddress((void**)&p_qkv, g_qkv);
    cudaGetSymbolAddress((void**)&p_ao,  g_ao);
    cudaGetSymbolAddress((void**)&p_x1,  g_x1);
    cudaGetSymbolAddress((void**)&p_w,   g_w);
    cudaGetSymbolAddress((void**)&p_ll,  g_ll);
    cudaGetSymbolAddress((void**)&p_cl,  g_cl);

    const int MB = NTOK / 128;  // 392

    // 1) LN1
    ln1_kernel<<<NTOK / 8, 256>>>(x, n1g, n1b, p_xln);

    // 2) QKV GEMM: (50176 x 96) @ (288 x 96)^T + b  -> g_qkv
    gemm2_k<1, false, false><<<dim3(MB, (QKVDIM + 127) / 128), 256>>>(
        p_xln, qkv_w, qkv_b, nullptr, nullptr, p_qkv,
        NTOK, QKVDIM, CDIM, QKVDIM);

    // 3) windowed attention core -> g_ao
    attn_kernel<<<NWIN, 128>>>(p_qkv, p_ao);

    // 4) proj + residual: x1 = x + ao @ proj_w^T + b
    gemm2_k<2, false, false><<<dim3(MB, 1), 256>>>(
        p_ao, proj_w, proj_b, x, nullptr, p_x1,
        NTOK, CDIM, CDIM, CDIM);

    // 5) double layernorm -> g_w
    ln2_kernel<<<NTOK / 8, 256>>>(p_x1, n2g, n2b, fng, fnb, p_w);

    // 6) pin GEMM + sigmoid + log-literals -> g_ll (token x 768)
    gemm2_k<3, false, false><<<dim3(MB, (HIDDIM + 127) / 128), 256>>>(
        p_w, pin_w, pin_b, nullptr, nullptr, p_ll,
        NTOK, HIDDIM, CDIM, LITDIM);

    // 7) clause GEMM with binary mask (tm_inc > 0), exp epilogue -> g_cl
    gemm2_k<4, false, true><<<dim3(MB, 1), 256>>>(
        p_ll, tm_inc, nullptr, nullptr, nullptr, p_cl,
        NTOK, NCLAUSE, LITDIM, NCLAUSE);

    // 8) logits = clauses @ tm_out (K x N layout), gated output + residual
    gemm2_k<5, true, false><<<dim3(MB, 1), 256>>>(
        p_cl, tm_out, nullptr, p_x1, gate, out,
        NTOK, CDIM, NCLAUSE, CDIM);

    (void)in_sizes; (void)n_in; (void)out_size;
}

// round 7
// speedup vs baseline: 2.8670x; 2.4656x over previous
#include <cuda_runtime.h>
#include <math.h>
#include <limits.h>

// Problem constants
#define NTOK 50176            // 16 * 56 * 56
#define CDIM 96
#define QKVDIM 288
#define HIDDIM 384
#define LITDIM 768
#define NCLAUSE 128
#define NWIN 1024             // 16 * 8 * 8
#define IMGHW 56
#define LNEPS 1e-5f

// ---------------- scratch (static device arrays; no allocation) -------------
__device__ float g_xln[(size_t)NTOK * CDIM];
__device__ float g_qkv[(size_t)NTOK * QKVDIM];
__device__ float g_ao [(size_t)NTOK * CDIM];
__device__ float g_x1 [(size_t)NTOK * CDIM];
__device__ float g_w  [(size_t)NTOK * CDIM];
__device__ float g_ll [(size_t)NTOK * LITDIM];
__device__ float g_cl [(size_t)NTOK * NCLAUSE];
__device__ int   g_skip;     // 1 => TM-FFN branch provably ~0, take fast path

// ---------------- helpers ---------------------------------------------------
__device__ __forceinline__ float warp_sum(float v) {
#pragma unroll
    for (int o = 16; o > 0; o >>= 1) v += __shfl_xor_sync(0xffffffffu, v, o);
    return v;
}

// ---------------- guard: is the clause branch provably negligible? ----------
// For every clause c, any literal pair (j, j+384) with BOTH mask bits set
// contributes log(max(y,eps)) + log(max(1-y,eps)) <= log(1/4) to the clause
// exponent S (true for ALL y in (0,1): y(1-y)<=1/4; eps cases even smaller).
// Hence S <= -1.386 * n_both(c) and
//   |logits| <= NCLAUSE * max|tm_out| * exp(-1.386 * min_c n_both(c)).
// If that bound < 1e-25, replacing logits by 0 perturbs the output by < 1e-25
// (|d out/d logits| <= 1), far below fp32 resolution: take the fast path.
__global__ void guard_kernel(const float* __restrict__ tm_inc,
                             const float* __restrict__ tm_out,
                             int* __restrict__ flag)
{
    __shared__ int   cnt[256];
    __shared__ float mxs[256];
    int t = threadIdx.x;
    int c = t >> 1, half = t & 1;
    int cn = 0;
    for (int j = half * 192; j < half * 192 + 192; j++) {
        float a = tm_inc[(size_t)c * LITDIM + j];
        float b = tm_inc[(size_t)c * LITDIM + HIDDIM + j];
        cn += (a > 0.0f && b > 0.0f) ? 1 : 0;
    }
    cnt[t] = cn;
    float m = 0.0f;
    for (int i = t; i < NCLAUSE * CDIM; i += 256)
        m = fmaxf(m, fabsf(tm_out[i]));
    mxs[t] = m;
    __syncthreads();
    if (t == 0) {
        int mn = INT_MAX;
        for (int i = 0; i < NCLAUSE; i++) {
            int v = cnt[2 * i] + cnt[2 * i + 1];
            mn = (v < mn) ? v : mn;
        }
        float M = 0.0f;
        for (int i = 0; i < 256; i++) M = fmaxf(M, mxs[i]);
        float logbound = logf((float)NCLAUSE * M + 1e-30f) - 1.3862944f * (float)mn;
        flag[0] = (logbound < -57.6f) ? 1 : 0;   // e^-57.6 ~ 1e-25
    }
}

// ---------------- LN kernels (warp per token, C = 96 = 3 * 32) ---------------
__global__ __launch_bounds__(256) void ln1_kernel(
    const float* __restrict__ x, const float* __restrict__ g,
    const float* __restrict__ b, float* __restrict__ y)
{
    int warp = (blockIdx.x * blockDim.x + threadIdx.x) >> 5;
    int lane = threadIdx.x & 31;
    if (warp >= NTOK) return;
    size_t base = (size_t)warp * CDIM;
    float v0 = x[base + lane];
    float v1 = x[base + lane + 32];
    float v2 = x[base + lane + 64];
    float mean = warp_sum(v0 + v1 + v2) * (1.0f / CDIM);
    float d0 = v0 - mean, d1 = v1 - mean, d2 = v2 - mean;
    float var = warp_sum(d0 * d0 + d1 * d1 + d2 * d2) * (1.0f / CDIM);
    float rs = rsqrtf(var + LNEPS);
    y[base + lane]      = d0 * rs * g[lane]      + b[lane];
    y[base + lane + 32] = d1 * rs * g[lane + 32] + b[lane + 32];
    y[base + lane + 64] = d2 * rs * g[lane + 64] + b[lane + 64];
}

// double layernorm: w = LN(LN(x1, g2, b2), fg, fb); early-exit on fast path
__global__ __launch_bounds__(256) void ln2_kernel(
    const float* __restrict__ x, const float* __restrict__ g2,
    const float* __restrict__ b2, const float* __restrict__ fg,
    const float* __restrict__ fb, float* __restrict__ y,
    const int* __restrict__ flag)
{
    if (flag[0]) return;
    int warp = (blockIdx.x * blockDim.x + threadIdx.x) >> 5;
    int lane = threadIdx.x & 31;
    if (warp >= NTOK) return;
    size_t base = (size_t)warp * CDIM;
    float v0 = x[base + lane];
    float v1 = x[base + lane + 32];
    float v2 = x[base + lane + 64];
    float mean = warp_sum(v0 + v1 + v2) * (1.0f / CDIM);
    float d0 = v0 - mean, d1 = v1 - mean, d2 = v2 - mean;
    float var = warp_sum(d0 * d0 + d1 * d1 + d2 * d2) * (1.0f / CDIM);
    float rs = rsqrtf(var + LNEPS);
    float z0 = d0 * rs * g2[lane]      + b2[lane];
    float z1 = d1 * rs * g2[lane + 32] + b2[lane + 32];
    float z2 = d2 * rs * g2[lane + 64] + b2[lane + 64];
    float m2 = warp_sum(z0 + z1 + z2) * (1.0f / CDIM);
    float e0 = z0 - m2, e1 = z1 - m2, e2 = z2 - m2;
    float var2 = warp_sum(e0 * e0 + e1 * e1 + e2 * e2) * (1.0f / CDIM);
    float rs2 = rsqrtf(var2 + LNEPS);
    y[base + lane]      = e0 * rs2 * fg[lane]      + fb[lane];
    y[base + lane + 32] = e1 * rs2 * fg[lane + 32] + fb[lane + 32];
    y[base + lane + 64] = e2 * rs2 * fg[lane + 64] + fb[lane + 64];
}

// ---------------- fp32 tiled GEMM, 128x128x16, 8x8 micro, double-buffered ----
// 2 CTAs/SM (128-reg cap). Modes as before. SKIP template:
//   0 = no flag interaction
//   1 = early-exit whole kernel when flag set (pin / clause GEMMs)
//   2 = on flag, write fast-path output: C = ex1 + (1-sigmoid(ex2[0]))*0.5
template<int MODE, bool BTRANS, bool BMASK, int SKIP>
__global__ __launch_bounds__(256, 2) void gemm2_k(
    const float* __restrict__ A, const float* __restrict__ B,
    const float* __restrict__ bias, const float* __restrict__ ex1,
    const float* __restrict__ ex2, float* __restrict__ C,
    int M, int N, int K, int ldc, const int* __restrict__ flag)
{
    const int BM = 128, BN = 128, BK = 16;

    int tid = threadIdx.x;
    int m0 = blockIdx.x * BM;
    int n0 = blockIdx.y * BN;
    int tx = tid & 15;        // n group
    int ty = tid >> 4;        // m group

    if (SKIP == 1) {
        if (flag[0]) return;
    }
    if (SKIP == 2) {
        if (flag[0]) {
            float gte = 1.0f / (1.0f + expf(-ex2[0]));
            float add = (1.0f - gte) * 0.5f;
#pragma unroll
            for (int i = 0; i < 8; i++) {
                int m = m0 + ty * 4 + (i < 4 ? i : 60 + i);
#pragma unroll
                for (int j = 0; j < 8; j++) {
                    int n = n0 + tx * 4 + (j < 4 ? j : 60 + j);
                    if (n >= N) continue;
                    C[(size_t)m * ldc + n] = ex1[(size_t)m * CDIM + n] + add;
                }
            }
            return;
        }
    }

    __shared__ __align__(16) float As[2][BK][BM + 4];
    __shared__ __align__(16) float Bs[2][BK][BN + 4];

    int lr = tid >> 1;        // row within tile for A/B(NxK) loads (0..127)
    int lk = (tid & 1) * 8;   // k offset (0 or 8)
    int bk = tid >> 4;        // k row for BTRANS B loads (0..15)
    int bn = (tid & 15) * 8;  // n offset for BTRANS B loads

    float acc[8][8];
#pragma unroll
    for (int i = 0; i < 8; i++)
#pragma unroll
        for (int j = 0; j < 8; j++) acc[i][j] = 0.0f;

    float ldA[8], ldB[8];
    int KT = K / BK;

#define GEMM_LOAD(kt)                                                        \
    {                                                                        \
        const float* ap = A + (size_t)(m0 + lr) * K + (kt) * BK + lk;        \
        *(float4*)&ldA[0] = *(const float4*)ap;                              \
        *(float4*)&ldA[4] = *(const float4*)(ap + 4);                        \
        if (!BTRANS) {                                                       \
            int n = n0 + lr;                                                 \
            if (n < N) {                                                     \
                const float* bp = B + (size_t)n * K + (kt) * BK + lk;        \
                *(float4*)&ldB[0] = *(const float4*)bp;                      \
                *(float4*)&ldB[4] = *(const float4*)(bp + 4);                \
            } else {                                                         \
                _Pragma("unroll")                                            \
                for (int j = 0; j < 8; j++) ldB[j] = 0.0f;                   \
            }                                                                \
            if (BMASK) {                                                     \
                _Pragma("unroll")                                            \
                for (int j = 0; j < 8; j++)                                  \
                    ldB[j] = (ldB[j] > 0.0f) ? 1.0f : 0.0f;                  \
            }                                                                \
        } else {                                                             \
            _Pragma("unroll")                                                \
            for (int j = 0; j < 8; j++) {                                    \
                int n = n0 + bn + j;                                         \
                ldB[j] = (n < N)                                             \
                    ? B[(size_t)((kt) * BK + bk) * N + n] : 0.0f;            \
            }                                                                \
        }                                                                    \
    }

#define GEMM_STS(bsel)                                                       \
    {                                                                        \
        _Pragma("unroll")                                                    \
        for (int j = 0; j < 8; j++) As[bsel][lk + j][lr] = ldA[j];           \
        if (!BTRANS) {                                                       \
            _Pragma("unroll")                                                \
            for (int j = 0; j < 8; j++) Bs[bsel][lk + j][lr] = ldB[j];       \
        } else {                                                             \
            _Pragma("unroll")                                                \
            for (int j = 0; j < 8; j++) Bs[bsel][bk][bn + j] = ldB[j];       \
        }                                                                    \
    }

    GEMM_LOAD(0);
    GEMM_STS(0);
    __syncthreads();

    int buf = 0;
    for (int kt = 0; kt < KT; kt++) {
        if (kt + 1 < KT) GEMM_LOAD(kt + 1);
#pragma unroll
        for (int k = 0; k < BK; k++) {
            float4 a0 = *(const float4*)&As[buf][k][ty * 4];
            float4 a1 = *(const float4*)&As[buf][k][ty * 4 + 64];
            float4 b0 = *(const float4*)&Bs[buf][k][tx * 4];
            float4 b1 = *(const float4*)&Bs[buf][k][tx * 4 + 64];
            float a[8] = {a0.x, a0.y, a0.z, a0.w, a1.x, a1.y, a1.z, a1.w};
            float b[8] = {b0.x, b0.y, b0.z, b0.w, b1.x, b1.y, b1.z, b1.w};
#pragma unroll
            for (int i = 0; i < 8; i++)
#pragma unroll
                for (int j = 0; j < 8; j++) acc[i][j] += a[i] * b[j];
        }
        if (kt + 1 < KT) {
            GEMM_STS(buf ^ 1);
            __syncthreads();
        }
        buf ^= 1;
    }

    // epilogue
    float gte = 0.0f;
    if (MODE == 5) gte = 1.0f / (1.0f + expf(-ex2[0]));
#pragma unroll
    for (int i = 0; i < 8; i++) {
        int m = m0 + ty * 4 + (i < 4 ? i : 60 + i);  // i>=4 -> +64+(i-4)
#pragma unroll
        for (int j = 0; j < 8; j++) {
            int n = n0 + tx * 4 + (j < 4 ? j : 60 + j);
            if (n >= N) continue;
            float v = acc[i][j];
            if (MODE == 1) {
                C[(size_t)m * ldc + n] = v + bias[n];
            } else if (MODE == 2) {
                C[(size_t)m * ldc + n] = ex1[(size_t)m * CDIM + n] + v + bias[n];
            } else if (MODE == 3) {
                float y = 1.0f / (1.0f + expf(-(v + bias[n])));
                C[(size_t)m * LITDIM + n]          = logf(fmaxf(y, 1e-6f));
                C[(size_t)m * LITDIM + HIDDIM + n] = logf(fmaxf(1.0f - y, 1e-6f));
            } else if (MODE == 4) {
                C[(size_t)m * ldc + n] = expf(v);
            } else if (MODE == 5) {
                float s = 1.0f / (1.0f + expf(-v));
                C[(size_t)m * ldc + n] = ex1[(size_t)m * CDIM + n] + gte * v + (1.0f - gte) * s;
            }
        }
    }
#undef GEMM_LOAD
#undef GEMM_STS
}

// ---------------- windowed attention core ------------------------------------
// One block per window (1024). qkv rows: [q(96) | k(96) | v(96)], head h at
// offset h*32.
// Input gather: token (wh,ww,th,tw) reads shifted image pos
//   ((wh*7+th+3)%56, (ww*7+tw+3)%56)                      -> ltab
// Output scatter (reference rolls WITHIN each window, axes (3,4), by +3):
//   a[wh][ww][th][tw] lands at image pos
//   (wh*7 + (th+3)%7, ww*7 + (tw+3)%7)                    -> otab
__global__ __launch_bounds__(128) void attn_kernel(
    const float* __restrict__ qkv, float* __restrict__ ao)
{
    __shared__ float qs[49][33], ks[49][33], vs[49][33];
    __shared__ float ps[49][52];
    __shared__ int ltab[49];
    __shared__ int otab[49];

    int w = blockIdx.x;
    int b  = w >> 6;
    int wh = (w >> 3) & 7;
    int ww = w & 7;
    int tid = threadIdx.x;

    if (tid < 49) {
        int th = tid / 7, tw = tid % 7;
        int r = (wh * 7 + th + 3) % IMGHW;
        int c = (ww * 7 + tw + 3) % IMGHW;
        ltab[tid] = b * (IMGHW * IMGHW) + r * IMGHW + c;
        int ro = wh * 7 + (th + 3) % 7;          // intra-window inverse roll
        int co = ww * 7 + (tw + 3) % 7;
        otab[tid] = b * (IMGHW * IMGHW) + ro * IMGHW + co;
    }
    __syncthreads();

    const float scale = 0.17677669529663687f;  // 1/sqrt(32)

    for (int h = 0; h < 3; h++) {
        for (int i = tid; i < 49 * 32; i += 128) {
            int t = i >> 5, d = i & 31;
            size_t base = (size_t)ltab[t] * QKVDIM + h * 32 + d;
            qs[t][d] = qkv[base];
            ks[t][d] = qkv[base + 96];
            vs[t][d] = qkv[base + 192];
        }
        __syncthreads();

        for (int i = tid; i < 49 * 49; i += 128) {
            int r = i / 49, c = i - r * 49;
            float s = 0.0f;
#pragma unroll
            for (int d = 0; d < 32; d++) s += qs[r][d] * ks[c][d];
            ps[r][c] = s * scale;
        }
        __syncthreads();

        if (tid < 49) {
            float mx = -1e30f;
            for (int j = 0; j < 49; j++) mx = fmaxf(mx, ps[tid][j]);
            float sum = 0.0f;
            for (int j = 0; j < 49; j++) {
                float e = expf(ps[tid][j] - mx);
                ps[tid][j] = e;
                sum += e;
            }
            float inv = 1.0f / sum;
            for (int j = 0; j < 49; j++) ps[tid][j] *= inv;
        }
        __syncthreads();

        for (int i = tid; i < 49 * 32; i += 128) {
            int t = i >> 5, d = i & 31;
            float o = 0.0f;
#pragma unroll
            for (int j = 0; j < 49; j++) o += ps[t][j] * vs[j][d];
            ao[(size_t)otab[t] * CDIM + h * 32 + d] = o;
        }
        __syncthreads();
    }
}

// ---------------- host launcher ----------------------------------------------
extern "C" void kernel_launch(void* const* d_in, const int* in_sizes, int n_in,
                              void* d_out, int out_size)
{
    const float* x       = (const float*)d_in[0];
    const float* n1g     = (const float*)d_in[1];
    const float* n1b     = (const float*)d_in[2];
    const float* qkv_w   = (const float*)d_in[3];
    const float* qkv_b   = (const float*)d_in[4];
    const float* proj_w  = (const float*)d_in[5];
    const float* proj_b  = (const float*)d_in[6];
    const float* n2g     = (const float*)d_in[7];
    const float* n2b     = (const float*)d_in[8];
    const float* fng     = (const float*)d_in[9];
    const float* fnb     = (const float*)d_in[10];
    const float* pin_w   = (const float*)d_in[11];
    const float* pin_b   = (const float*)d_in[12];
    const float* tm_inc  = (const float*)d_in[13];
    const float* tm_out  = (const float*)d_in[14];
    const float* gate    = (const float*)d_in[15];
    float* out           = (float*)d_out;

    float *p_xln, *p_qkv, *p_ao, *p_x1, *p_w, *p_ll, *p_cl;
    int* p_skip;
    cudaGetSymbolAddress((void**)&p_xln, g_xln);
    cudaGetSymbolAddress((void**)&p_qkv, g_qkv);
    cudaGetSymbolAddress((void**)&p_ao,  g_ao);
    cudaGetSymbolAddress((void**)&p_x1,  g_x1);
    cudaGetSymbolAddress((void**)&p_w,   g_w);
    cudaGetSymbolAddress((void**)&p_ll,  g_ll);
    cudaGetSymbolAddress((void**)&p_cl,  g_cl);
    cudaGetSymbolAddress((void**)&p_skip, g_skip);

    const int MB = NTOK / 128;  // 392

    // 0) guard: decide whether the clause branch is provably negligible
    guard_kernel<<<1, 256>>>(tm_inc, tm_out, p_skip);

    // 1) LN1
    ln1_kernel<<<NTOK / 8, 256>>>(x, n1g, n1b, p_xln);

    // 2) QKV GEMM: (50176 x 96) @ (288 x 96)^T + b  -> g_qkv
    gemm2_k<1, false, false, 0><<<dim3(MB, (QKVDIM + 127) / 128), 256>>>(
        p_xln, qkv_w, qkv_b, nullptr, nullptr, p_qkv,
        NTOK, QKVDIM, CDIM, QKVDIM, p_skip);

    // 3) windowed attention core -> g_ao
    attn_kernel<<<NWIN, 128>>>(p_qkv, p_ao);

    // 4) proj + residual: x1 = x + ao @ proj_w^T + b
    gemm2_k<2, false, false, 0><<<dim3(MB, 1), 256>>>(
        p_ao, proj_w, proj_b, x, nullptr, p_x1,
        NTOK, CDIM, CDIM, CDIM, p_skip);

    // 5) double layernorm -> g_w   (skipped on fast path)
    ln2_kernel<<<NTOK / 8, 256>>>(p_x1, n2g, n2b, fng, fnb, p_w, p_skip);

    // 6) pin GEMM + sigmoid + log-literals -> g_ll   (skipped on fast path)
    gemm2_k<3, false, false, 1><<<dim3(MB, (HIDDIM + 127) / 128), 256>>>(
        p_w, pin_w, pin_b, nullptr, nullptr, p_ll,
        NTOK, HIDDIM, CDIM, LITDIM, p_skip);

    // 7) clause GEMM, binary mask, exp epilogue -> g_cl (skipped on fast path)
    gemm2_k<4, false, true, 1><<<dim3(MB, 1), 256>>>(
        p_ll, tm_inc, nullptr, nullptr, nullptr, p_cl,
        NTOK, NCLAUSE, LITDIM, NCLAUSE, p_skip);

    // 8) final: full GEMM normally; on fast path writes x1 + (1-g)*0.5
    gemm2_k<5, true, false, 2><<<dim3(MB, 1), 256>>>(
        p_cl, tm_out, nullptr, p_x1, gate, out,
        NTOK, CDIM, NCLAUSE, CDIM, p_skip);

    (void)in_sizes; (void)n_in; (void)out_size;
}

// round 8
// speedup vs baseline: 3.6116x; 1.2597x over previous
#include <cuda_runtime.h>
#include <math.h>
#include <limits.h>

// Problem constants
#define NTOK 50176            // 16 * 56 * 56
#define CDIM 96
#define QKVDIM 288
#define HIDDIM 384
#define LITDIM 768
#define NCLAUSE 128
#define NWIN 1024             // 16 * 8 * 8
#define IMGHW 56
#define LNEPS 1e-5f

// ---------------- scratch (static device arrays; no allocation) -------------
__device__ float g_xln[(size_t)NTOK * CDIM];
__device__ float g_qkv[(size_t)NTOK * QKVDIM];
__device__ float g_ao [(size_t)NTOK * CDIM];
__device__ float g_x1 [(size_t)NTOK * CDIM];
__device__ float g_w  [(size_t)NTOK * CDIM];
__device__ float g_ll [(size_t)NTOK * LITDIM];
__device__ float g_cl [(size_t)NTOK * NCLAUSE];
__device__ int   g_skip;     // 1 => TM-FFN branch provably ~0, take fast path

// ---------------- helpers ---------------------------------------------------
__device__ __forceinline__ float warp_sum(float v) {
#pragma unroll
    for (int o = 16; o > 0; o >>= 1) v += __shfl_xor_sync(0xffffffffu, v, o);
    return v;
}

// ---------------- guard: is the clause branch provably negligible? ----------
// For every clause c, any literal pair (j, j+384) with BOTH mask bits set
// contributes log(max(y,eps)) + log(max(1-y,eps)) <= log(1/4) to the clause
// exponent S (true for ALL y in (0,1): y(1-y)<=1/4; eps cases even smaller).
// Hence S <= -1.386 * n_both(c) and
//   |logits| <= NCLAUSE * max|tm_out| * exp(-1.386 * min_c n_both(c)).
// If that bound < 1e-25, replacing logits by 0 perturbs the output by < 1e-25
// (|d out/d logits| <= 1), far below fp32 resolution: take the fast path.
__global__ void guard_kernel(const float* __restrict__ tm_inc,
                             const float* __restrict__ tm_out,
                             int* __restrict__ flag)
{
    __shared__ int   cnt[256];
    __shared__ float mxs[256];
    int t = threadIdx.x;
    int c = t >> 1, half = t & 1;
    int cn = 0;
    for (int j = half * 192; j < half * 192 + 192; j++) {
        float a = tm_inc[(size_t)c * LITDIM + j];
        float b = tm_inc[(size_t)c * LITDIM + HIDDIM + j];
        cn += (a > 0.0f && b > 0.0f) ? 1 : 0;
    }
    cnt[t] = cn;
    float m = 0.0f;
    for (int i = t; i < NCLAUSE * CDIM; i += 256)
        m = fmaxf(m, fabsf(tm_out[i]));
    mxs[t] = m;
    __syncthreads();
    if (t == 0) {
        int mn = INT_MAX;
        for (int i = 0; i < NCLAUSE; i++) {
            int v = cnt[2 * i] + cnt[2 * i + 1];
            mn = (v < mn) ? v : mn;
        }
        float M = 0.0f;
        for (int i = 0; i < 256; i++) M = fmaxf(M, mxs[i]);
        float logbound = logf((float)NCLAUSE * M + 1e-30f) - 1.3862944f * (float)mn;
        flag[0] = (logbound < -57.6f) ? 1 : 0;   // e^-57.6 ~ 1e-25
    }
}

// ---------------- LN kernels (warp per token, C = 96 = 3 * 32) ---------------
__global__ __launch_bounds__(256) void ln1_kernel(
    const float* __restrict__ x, const float* __restrict__ g,
    const float* __restrict__ b, float* __restrict__ y)
{
    int warp = (blockIdx.x * blockDim.x + threadIdx.x) >> 5;
    int lane = threadIdx.x & 31;
    if (warp >= NTOK) return;
    size_t base = (size_t)warp * CDIM;
    float v0 = x[base + lane];
    float v1 = x[base + lane + 32];
    float v2 = x[base + lane + 64];
    float mean = warp_sum(v0 + v1 + v2) * (1.0f / CDIM);
    float d0 = v0 - mean, d1 = v1 - mean, d2 = v2 - mean;
    float var = warp_sum(d0 * d0 + d1 * d1 + d2 * d2) * (1.0f / CDIM);
    float rs = rsqrtf(var + LNEPS);
    y[base + lane]      = d0 * rs * g[lane]      + b[lane];
    y[base + lane + 32] = d1 * rs * g[lane + 32] + b[lane + 32];
    y[base + lane + 64] = d2 * rs * g[lane + 64] + b[lane + 64];
}

// double layernorm: w = LN(LN(x1, g2, b2), fg, fb); early-exit on fast path
__global__ __launch_bounds__(256) void ln2_kernel(
    const float* __restrict__ x, const float* __restrict__ g2,
    const float* __restrict__ b2, const float* __restrict__ fg,
    const float* __restrict__ fb, float* __restrict__ y,
    const int* __restrict__ flag)
{
    if (flag[0]) return;
    int warp = (blockIdx.x * blockDim.x + threadIdx.x) >> 5;
    int lane = threadIdx.x & 31;
    if (warp >= NTOK) return;
    size_t base = (size_t)warp * CDIM;
    float v0 = x[base + lane];
    float v1 = x[base + lane + 32];
    float v2 = x[base + lane + 64];
    float mean = warp_sum(v0 + v1 + v2) * (1.0f / CDIM);
    float d0 = v0 - mean, d1 = v1 - mean, d2 = v2 - mean;
    float var = warp_sum(d0 * d0 + d1 * d1 + d2 * d2) * (1.0f / CDIM);
    float rs = rsqrtf(var + LNEPS);
    float z0 = d0 * rs * g2[lane]      + b2[lane];
    float z1 = d1 * rs * g2[lane + 32] + b2[lane + 32];
    float z2 = d2 * rs * g2[lane + 64] + b2[lane + 64];
    float m2 = warp_sum(z0 + z1 + z2) * (1.0f / CDIM);
    float e0 = z0 - m2, e1 = z1 - m2, e2 = z2 - m2;
    float var2 = warp_sum(e0 * e0 + e1 * e1 + e2 * e2) * (1.0f / CDIM);
    float rs2 = rsqrtf(var2 + LNEPS);
    y[base + lane]      = e0 * rs2 * fg[lane]      + fb[lane];
    y[base + lane + 32] = e1 * rs2 * fg[lane + 32] + fb[lane + 32];
    y[base + lane + 64] = e2 * rs2 * fg[lane + 64] + fb[lane + 64];
}

// ---------------- fp32 GEMM, BN=96 exact (qkv / proj), 8x6 micro -------------
// C[M x N] = A[M x K] @ B^T (+bias), B is N x K. N must be a multiple of 96.
// MODE 1: C = acc + bias[n]
// MODE 2: C = ex1[m*96+n] + acc + bias[n]
template<int MODE>
__global__ __launch_bounds__(256, 2) void gemm96_k(
    const float* __restrict__ A, const float* __restrict__ B,
    const float* __restrict__ bias, const float* __restrict__ ex1,
    float* __restrict__ C, int M, int N, int K, int ldc)
{
    const int BM = 128, BN = 96, BK = 16;
    __shared__ __align__(16) float As[2][BK][BM + 4];
    __shared__ __align__(16) float Bs[2][BK][BN + 4];

    int tid = threadIdx.x;
    int m0 = blockIdx.x * BM;
    int n0 = blockIdx.y * BN;
    int tx = tid & 15;        // 16 col groups of 6
    int ty = tid >> 4;        // 16 row groups

    int lr = tid >> 1;        // A row (0..127)
    int lk = (tid & 1) * 8;   // A k offset
    int br = tid >> 1;        // B row (0..95) for tid<192
    int bk2 = (tid & 1) * 8;

    float acc[8][6];
#pragma unroll
    for (int i = 0; i < 8; i++)
#pragma unroll
        for (int j = 0; j < 6; j++) acc[i][j] = 0.0f;

    float ldA[8], ldB[8];
    int KT = K / BK;

#define G96_LOAD(kt)                                                         \
    {                                                                        \
        const float* ap = A + (size_t)(m0 + lr) * K + (kt) * BK + lk;        \
        *(float4*)&ldA[0] = *(const float4*)ap;                              \
        *(float4*)&ldA[4] = *(const float4*)(ap + 4);                        \
        if (tid < 192) {                                                     \
            const float* bp = B + (size_t)(n0 + br) * K + (kt) * BK + bk2;   \
            *(float4*)&ldB[0] = *(const float4*)bp;                          \
            *(float4*)&ldB[4] = *(const float4*)(bp + 4);                    \
        }                                                                    \
    }

#define G96_STS(bsel)                                                        \
    {                                                                        \
        _Pragma("unroll")                                                    \
        for (int j = 0; j < 8; j++) As[bsel][lk + j][lr] = ldA[j];           \
        if (tid < 192) {                                                     \
            _Pragma("unroll")                                                \
            for (int j = 0; j < 8; j++) Bs[bsel][bk2 + j][br] = ldB[j];      \
        }                                                                    \
    }

    G96_LOAD(0);
    G96_STS(0);
    __syncthreads();

    int buf = 0;
    for (int kt = 0; kt < KT; kt++) {
        if (kt + 1 < KT) G96_LOAD(kt + 1);
#pragma unroll
        for (int k = 0; k < BK; k++) {
            float4 a0 = *(const float4*)&As[buf][k][ty * 4];
            float4 a1 = *(const float4*)&As[buf][k][ty * 4 + 64];
            float a[8] = {a0.x, a0.y, a0.z, a0.w, a1.x, a1.y, a1.z, a1.w};
            float b[6];
#pragma unroll
            for (int j = 0; j < 6; j++) b[j] = Bs[buf][k][tx * 6 + j];
#pragma unroll
            for (int i = 0; i < 8; i++)
#pragma unroll
                for (int j = 0; j < 6; j++) acc[i][j] += a[i] * b[j];
        }
        if (kt + 1 < KT) {
            G96_STS(buf ^ 1);
            __syncthreads();
        }
        buf ^= 1;
    }

#pragma unroll
    for (int i = 0; i < 8; i++) {
        int m = m0 + ty * 4 + (i < 4 ? i : 60 + i);
#pragma unroll
        for (int j = 0; j < 6; j++) {
            int n = n0 + tx * 6 + j;
            float v = acc[i][j];
            if (MODE == 1) {
                C[(size_t)m * ldc + n] = v + bias[n];
            } else {
                C[(size_t)m * ldc + n] = ex1[(size_t)m * CDIM + n] + v + bias[n];
            }
        }
    }
#undef G96_LOAD
#undef G96_STS
}

// ---------------- fp32 tiled GEMM, 128x128x16, 8x8 micro (modes 3,4,5) -------
// SKIP: 1 = early-exit whole kernel when flag set; 2 = fast-path final write.
template<int MODE, bool BTRANS, bool BMASK, int SKIP>
__global__ __launch_bounds__(256, 2) void gemm2_k(
    const float* __restrict__ A, const float* __restrict__ B,
    const float* __restrict__ bias, const float* __restrict__ ex1,
    const float* __restrict__ ex2, float* __restrict__ C,
    int M, int N, int K, int ldc, const int* __restrict__ flag)
{
    const int BM = 128, BN = 128, BK = 16;

    int tid = threadIdx.x;
    int m0 = blockIdx.x * BM;
    int n0 = blockIdx.y * BN;
    int tx = tid & 15;
    int ty = tid >> 4;

    if (SKIP == 1) {
        if (flag[0]) return;
    }
    if (SKIP == 2) {
        if (flag[0]) {
            float gte = 1.0f / (1.0f + expf(-ex2[0]));
            float add = (1.0f - gte) * 0.5f;
#pragma unroll
            for (int i = 0; i < 8; i++) {
                int m = m0 + ty * 4 + (i < 4 ? i : 60 + i);
#pragma unroll
                for (int j = 0; j < 8; j++) {
                    int n = n0 + tx * 4 + (j < 4 ? j : 60 + j);
                    if (n >= N) continue;
                    C[(size_t)m * ldc + n] = ex1[(size_t)m * CDIM + n] + add;
                }
            }
            return;
        }
    }

    __shared__ __align__(16) float As[2][BK][BM + 4];
    __shared__ __align__(16) float Bs[2][BK][BN + 4];

    int lr = tid >> 1;
    int lk = (tid & 1) * 8;
    int bk = tid >> 4;
    int bn = (tid & 15) * 8;

    float acc[8][8];
#pragma unroll
    for (int i = 0; i < 8; i++)
#pragma unroll
        for (int j = 0; j < 8; j++) acc[i][j] = 0.0f;

    float ldA[8], ldB[8];
    int KT = K / BK;

#define GEMM_LOAD(kt)                                                        \
    {                                                                        \
        const float* ap = A + (size_t)(m0 + lr) * K + (kt) * BK + lk;        \
        *(float4*)&ldA[0] = *(const float4*)ap;                              \
        *(float4*)&ldA[4] = *(const float4*)(ap + 4);                        \
        if (!BTRANS) {                                                       \
            int n = n0 + lr;                                                 \
            if (n < N) {                                                     \
                const float* bp = B + (size_t)n * K + (kt) * BK + lk;        \
                *(float4*)&ldB[0] = *(const float4*)bp;                      \
                *(float4*)&ldB[4] = *(const float4*)(bp + 4);                \
            } else {                                                         \
                _Pragma("unroll")                                            \
                for (int j = 0; j < 8; j++) ldB[j] = 0.0f;                   \
            }                                                                \
            if (BMASK) {                                                     \
                _Pragma("unroll")                                            \
                for (int j = 0; j < 8; j++)                                  \
                    ldB[j] = (ldB[j] > 0.0f) ? 1.0f : 0.0f;                  \
            }                                                                \
        } else {                                                             \
            _Pragma("unroll")                                                \
            for (int j = 0; j < 8; j++) {                                    \
                int n = n0 + bn + j;                                         \
                ldB[j] = (n < N)                                             \
                    ? B[(size_t)((kt) * BK + bk) * N + n] : 0.0f;            \
            }                                                                \
        }                                                                    \
    }

#define GEMM_STS(bsel)                                                       \
    {                                                                        \
        _Pragma("unroll")                                                    \
        for (int j = 0; j < 8; j++) As[bsel][lk + j][lr] = ldA[j];           \
        if (!BTRANS) {                                                       \
            _Pragma("unroll")                                                \
            for (int j = 0; j < 8; j++) Bs[bsel][lk + j][lr] = ldB[j];       \
        } else {                                                             \
            _Pragma("unroll")                                                \
            for (int j = 0; j < 8; j++) Bs[bsel][bk][bn + j] = ldB[j];       \
        }                                                                    \
    }

    GEMM_LOAD(0);
    GEMM_STS(0);
    __syncthreads();

    int buf = 0;
    for (int kt = 0; kt < KT; kt++) {
        if (kt + 1 < KT) GEMM_LOAD(kt + 1);
#pragma unroll
        for (int k = 0; k < BK; k++) {
            float4 a0 = *(const float4*)&As[buf][k][ty * 4];
            float4 a1 = *(const float4*)&As[buf][k][ty * 4 + 64];
            float4 b0 = *(const float4*)&Bs[buf][k][tx * 4];
            float4 b1 = *(const float4*)&Bs[buf][k][tx * 4 + 64];
            float a[8] = {a0.x, a0.y, a0.z, a0.w, a1.x, a1.y, a1.z, a1.w};
            float b[8] = {b0.x, b0.y, b0.z, b0.w, b1.x, b1.y, b1.z, b1.w};
#pragma unroll
            for (int i = 0; i < 8; i++)
#pragma unroll
                for (int j = 0; j < 8; j++) acc[i][j] += a[i] * b[j];
        }
        if (kt + 1 < KT) {
            GEMM_STS(buf ^ 1);
            __syncthreads();
        }
        buf ^= 1;
    }

    float gte = 0.0f;
    if (MODE == 5) gte = 1.0f / (1.0f + expf(-ex2[0]));
#pragma unroll
    for (int i = 0; i < 8; i++) {
        int m = m0 + ty * 4 + (i < 4 ? i : 60 + i);
#pragma unroll
        for (int j = 0; j < 8; j++) {
            int n = n0 + tx * 4 + (j < 4 ? j : 60 + j);
            if (n >= N) continue;
            float v = acc[i][j];
            if (MODE == 3) {
                float y = 1.0f / (1.0f + expf(-(v + bias[n])));
                C[(size_t)m * LITDIM + n]          = logf(fmaxf(y, 1e-6f));
                C[(size_t)m * LITDIM + HIDDIM + n] = logf(fmaxf(1.0f - y, 1e-6f));
            } else if (MODE == 4) {
                C[(size_t)m * ldc + n] = expf(v);
            } else if (MODE == 5) {
                float s = 1.0f / (1.0f + expf(-v));
                C[(size_t)m * ldc + n] = ex1[(size_t)m * CDIM + n] + gte * v + (1.0f - gte) * s;
            }
        }
    }
#undef GEMM_LOAD
#undef GEMM_STS
}

// ---------------- windowed attention, one block per (window, head) -----------
// grid (NWIN, 3), block 128. Vectorized LDS.128 micro-tiles.
// Input gather: token (wh,ww,th,tw) reads shifted image pos
//   ((wh*7+th+3)%56, (ww*7+tw+3)%56)                      -> ltab
// Output scatter (intra-window inverse roll by +3):
//   (wh*7 + (th+3)%7, ww*7 + (tw+3)%7)                    -> otab
__global__ __launch_bounds__(128) void attn2_kernel(
    const float* __restrict__ qkv, float* __restrict__ ao)
{
    __shared__ __align__(16) float qs[50][44];   // row pad 44: conflict-free LDS.128
    __shared__ __align__(16) float ks[50][44];
    __shared__ __align__(16) float vs[49][44];
    __shared__ float ps[52][53];
    __shared__ int ltab[49];
    __shared__ int otab[49];

    int w  = blockIdx.x;
    int h  = blockIdx.y;
    int b  = w >> 6;
    int wh = (w >> 3) & 7;
    int ww = w & 7;
    int tid = threadIdx.x;

    if (tid < 49) {
        int th = tid / 7, tw = tid % 7;
        int r = (wh * 7 + th + 3) % IMGHW;
        int c = (ww * 7 + tw + 3) % IMGHW;
        ltab[tid] = b * (IMGHW * IMGHW) + r * IMGHW + c;
        int ro = wh * 7 + (th + 3) % 7;
        int co = ww * 7 + (tw + 3) % 7;
        otab[tid] = b * (IMGHW * IMGHW) + ro * IMGHW + co;
    }
    __syncthreads();

    // load q/k/v for this head: 49 tokens x 8 d-quads
    for (int i = tid; i < 49 * 8; i += 128) {
        int t = i >> 3, dq = (i & 7) * 4;
        const float* base = qkv + (size_t)ltab[t] * QKVDIM + h * 32 + dq;
        *(float4*)&qs[t][dq] = *(const float4*)base;
        *(float4*)&ks[t][dq] = *(const float4*)(base + 96);
        *(float4*)&vs[t][dq] = *(const float4*)(base + 192);
    }
    __syncthreads();

    const float scale = 0.17677669529663687f;  // 1/sqrt(32)

    // scores: 25x25 grid of 2x2 tiles (pad row 49 read, writes guarded)
    for (int tile = tid; tile < 625; tile += 128) {
        int rp = tile % 25, cp = tile / 25;
        int r0 = rp * 2, c0 = cp * 2;
        float a00 = 0.0f, a01 = 0.0f, a10 = 0.0f, a11 = 0.0f;
#pragma unroll
        for (int dq = 0; dq < 32; dq += 4) {
            float4 qa = *(const float4*)&qs[r0][dq];
            float4 qb = *(const float4*)&qs[r0 + 1][dq];
            float4 ka = *(const float4*)&ks[c0][dq];
            float4 kb = *(const float4*)&ks[c0 + 1][dq];
            a00 += qa.x * ka.x + qa.y * ka.y + qa.z * ka.z + qa.w * ka.w;
            a01 += qa.x * kb.x + qa.y * kb.y + qa.z * kb.z + qa.w * kb.w;
            a10 += qb.x * ka.x + qb.y * ka.y + qb.z * ka.z + qb.w * ka.w;
            a11 += qb.x * kb.x + qb.y * kb.y + qb.z * kb.z + qb.w * kb.w;
        }
        ps[r0][c0] = a00 * scale;
        if (c0 + 1 < 49) ps[r0][c0 + 1] = a01 * scale;
        if (r0 + 1 < 49) {
            ps[r0 + 1][c0] = a10 * scale;
            if (c0 + 1 < 49) ps[r0 + 1][c0 + 1] = a11 * scale;
        }
    }
    __syncthreads();

    // softmax per row
    if (tid < 49) {
        float mx = -1e30f;
        for (int j = 0; j < 49; j++) mx = fmaxf(mx, ps[tid][j]);
        float sum = 0.0f;
        for (int j = 0; j < 49; j++) {
            float e = expf(ps[tid][j] - mx);
            ps[tid][j] = e;
            sum += e;
        }
        float inv = 1.0f / sum;
        for (int j = 0; j < 49; j++) ps[tid][j] *= inv;
    }
    __syncthreads();

    // AV: 13 token-groups x 8 d-quads = 104 tiles; 4 tokens x 4 dims each
    for (int tile = tid; tile < 104; tile += 128) {
        int tg = tile >> 3, dq = (tile & 7) * 4;
        int t0 = tg * 4;
        float acc[4][4];
#pragma unroll
        for (int i = 0; i < 4; i++)
#pragma unroll
            for (int j = 0; j < 4; j++) acc[i][j] = 0.0f;
        for (int j = 0; j < 49; j++) {
            float4 v4 = *(const float4*)&vs[j][dq];
#pragma unroll
            for (int it = 0; it < 4; it++) {
                float p = ps[t0 + it][j];   // rows 49..51 garbage, never stored
                acc[it][0] += p * v4.x;
                acc[it][1] += p * v4.y;
                acc[it][2] += p * v4.z;
                acc[it][3] += p * v4.w;
            }
        }
#pragma unroll
        for (int it = 0; it < 4; it++) {
            int t = t0 + it;
            if (t < 49) {
                float4 o = {acc[it][0], acc[it][1], acc[it][2], acc[it][3]};
                *(float4*)&ao[(size_t)otab[t] * CDIM + h * 32 + dq] = o;
            }
        }
    }
}

// ---------------- host launcher ----------------------------------------------
extern "C" void kernel_launch(void* const* d_in, const int* in_sizes, int n_in,
                              void* d_out, int out_size)
{
    const float* x       = (const float*)d_in[0];
    const float* n1g     = (const float*)d_in[1];
    const float* n1b     = (const float*)d_in[2];
    const float* qkv_w   = (const float*)d_in[3];
    const float* qkv_b   = (const float*)d_in[4];
    const float* proj_w  = (const float*)d_in[5];
    const float* proj_b  = (const float*)d_in[6];
    const float* n2g     = (const float*)d_in[7];
    const float* n2b     = (const float*)d_in[8];
    const float* fng     = (const float*)d_in[9];
    const float* fnb     = (const float*)d_in[10];
    const float* pin_w   = (const float*)d_in[11];
    const float* pin_b   = (const float*)d_in[12];
    const float* tm_inc  = (const float*)d_in[13];
    const float* tm_out  = (const float*)d_in[14];
    const float* gate    = (const float*)d_in[15];
    float* out           = (float*)d_out;

    float *p_xln, *p_qkv, *p_ao, *p_x1, *p_w, *p_ll, *p_cl;
    int* p_skip;
    cudaGetSymbolAddress((void**)&p_xln, g_xln);
    cudaGetSymbolAddress((void**)&p_qkv, g_qkv);
    cudaGetSymbolAddress((void**)&p_ao,  g_ao);
    cudaGetSymbolAddress((void**)&p_x1,  g_x1);
    cudaGetSymbolAddress((void**)&p_w,   g_w);
    cudaGetSymbolAddress((void**)&p_ll,  g_ll);
    cudaGetSymbolAddress((void**)&p_cl,  g_cl);
    cudaGetSymbolAddress((void**)&p_skip, g_skip);

    const int MB = NTOK / 128;  // 392

    // 0) guard: decide whether the clause branch is provably negligible
    guard_kernel<<<1, 256>>>(tm_inc, tm_out, p_skip);

    // 1) LN1
    ln1_kernel<<<NTOK / 8, 256>>>(x, n1g, n1b, p_xln);

    // 2) QKV GEMM: (50176 x 96) @ (288 x 96)^T + b, 3 exact BN=96 tiles
    gemm96_k<1><<<dim3(MB, QKVDIM / 96), 256>>>(
        p_xln, qkv_w, qkv_b, nullptr, p_qkv, NTOK, QKVDIM, CDIM, QKVDIM);

    // 3) windowed attention: one block per (window, head)
    attn2_kernel<<<dim3(NWIN, 3), 128>>>(p_qkv, p_ao);

    // 4) proj + residual: x1 = x + ao @ proj_w^T + b, 1 exact BN=96 tile
    gemm96_k<2><<<dim3(MB, 1), 256>>>(
        p_ao, proj_w, proj_b, x, p_x1, NTOK, CDIM, CDIM, CDIM);

    // 5) double layernorm -> g_w   (skipped on fast path)
    ln2_kernel<<<NTOK / 8, 256>>>(p_x1, n2g, n2b, fng, fnb, p_w, p_skip);

    // 6) pin GEMM + sigmoid + log-literals -> g_ll   (skipped on fast path)
    gemm2_k<3, false, false, 1><<<dim3(MB, (HIDDIM + 127) / 128), 256>>>(
        p_w, pin_w, pin_b, nullptr, nullptr, p_ll,
        NTOK, HIDDIM, CDIM, LITDIM, p_skip);

    // 7) clause GEMM, binary mask, exp epilogue -> g_cl (skipped on fast path)
    gemm2_k<4, false, true, 1><<<dim3(MB, 1), 256>>>(
        p_ll, tm_inc, nullptr, nullptr, nullptr, p_cl,
        NTOK, NCLAUSE, LITDIM, NCLAUSE, p_skip);

    // 8) final: full GEMM normally; on fast path writes x1 + (1-g)*0.5
    gemm2_k<5, true, false, 2><<<dim3(MB, 1), 256>>>(
        p_cl, tm_out, nullptr, p_x1, gate, out,
        NTOK, CDIM, NCLAUSE, CDIM, p_skip);

    (void)in_sizes; (void)n_in; (void)out_size;
}